// round 5
// baseline (speedup 1.0000x reference)
#include <cuda_runtime.h>
#include <cstdint>

#define N_MAX 50000
#define E_MAX 800000
#define IN_DIM 128
#define HEADS 4
#define OUT_DIM 32
#define OC (HEADS*OUT_DIM)   // 128
#define NEG_SLOPE 0.2f
#define EPS_F 1e-16f

// ---------------- scratch (no allocations allowed; 16B-aligned for vector ops) ----------------
__device__ __align__(16) float    g_h[N_MAX * OC];          // 25.6 MB
__device__ __align__(16) float    g_asrc[N_MAX * HEADS];
__device__ __align__(16) float    g_adst[N_MAX * HEADS];
__device__ __align__(16) unsigned g_mbits[N_MAX * HEADS];   // order-encoded max
__device__ __align__(16) float    g_s[N_MAX * HEADS];
__device__ int g_idx64;   // 1 if edge_index is int64, 0 if int32

// ---------------- helpers ----------------
__device__ __forceinline__ unsigned enc_f(float f) {
    unsigned u = __float_as_uint(f);
    return (u & 0x80000000u) ? ~u : (u | 0x80000000u);
}
__device__ __forceinline__ float dec_f(unsigned b) {
    return (b & 0x80000000u) ? __uint_as_float(b ^ 0x80000000u)
                             : __uint_as_float(~b);
}
__device__ __forceinline__ void red_add_v4(float* p, float4 v) {
    asm volatile("red.global.add.v4.f32 [%0], {%1,%2,%3,%4};"
                 :: "l"(p), "f"(v.x), "f"(v.y), "f"(v.z), "f"(v.w) : "memory");
}
__device__ __forceinline__ float lrelu(float a) {
    return a > 0.f ? a : NEG_SLOPE * a;
}
// flag-guarded edge index loader (src, dst)
__device__ __forceinline__ int2 load_edge(const void* ei, int e, int eidx) {
    if (g_idx64) {
        const long long* p = (const long long*)ei;
        return make_int2((int)p[eidx], (int)p[e + eidx]);
    } else {
        const int* p = (const int*)ei;
        return make_int2(p[eidx], p[e + eidx]);
    }
}

// ---------------- K-1: detect edge_index dtype ----------------
__global__ void k_detect(const unsigned* __restrict__ raw) {
    // int64 little-endian of small non-negative values => odd 32-bit words all 0
    unsigned any = 0;
    for (int i = threadIdx.x; i < 128; i += 32) any |= raw[2 * i + 1];
#pragma unroll
    for (int o = 16; o > 0; o >>= 1) any |= __shfl_down_sync(0xffffffffu, any, o);
    if (threadIdx.x == 0) g_idx64 = (any == 0u) ? 1 : 0;
}

// ---------------- K0: init out=bias, m=-inf(enc 0), s=0 ----------------
__global__ void k_init(const float* __restrict__ bias, float* __restrict__ out, int n) {
    int idx = blockIdx.x * blockDim.x + threadIdx.x;
    int tot = n * OC;
    if (idx < tot) out[idx] = bias[idx & (OC - 1)];
    if (idx < n * HEADS) { g_mbits[idx] = 0u; g_s[idx] = 0.f; }
}

// ---------------- K1: h = x @ W^T (fp32, smem-tiled) ----------------
#define TM 64
#define WS_S 132
#define XS_S 68
__global__ void k_gemm(const float* __restrict__ x, const float* __restrict__ W,
                       int n) {
    extern __shared__ float sm[];
    float* ws = sm;                 // 128*132
    float* xs = sm + IN_DIM * WS_S; // 128*68
    int tid = threadIdx.x;
    int tx = tid & 15, ty = tid >> 4;
    int row0 = blockIdx.x * TM;

    // load W transposed: ws[k][c] = W[c][k]
    for (int idx = tid; idx < OC * IN_DIM; idx += 256) {
        int c = idx >> 7, k = idx & 127;
        ws[k * WS_S + c] = W[idx];
    }
    // load x tile transposed: xs[k][r] = x[row0+r][k]
    for (int idx = tid; idx < TM * IN_DIM; idx += 256) {
        int r = idx >> 7, k = idx & 127;
        int row = row0 + r;
        xs[k * XS_S + r] = (row < n) ? x[row * IN_DIM + k] : 0.f;
    }
    __syncthreads();

    float acc[4][8];
#pragma unroll
    for (int i = 0; i < 4; i++)
#pragma unroll
        for (int j = 0; j < 8; j++) acc[i][j] = 0.f;

#pragma unroll 8
    for (int k = 0; k < IN_DIM; k++) {
        float4 a  = *(const float4*)&xs[k * XS_S + ty * 4];
        float4 b0 = *(const float4*)&ws[k * WS_S + tx * 8];
        float4 b1 = *(const float4*)&ws[k * WS_S + tx * 8 + 4];
        float av[4] = {a.x, a.y, a.z, a.w};
        float bv[8] = {b0.x, b0.y, b0.z, b0.w, b1.x, b1.y, b1.z, b1.w};
#pragma unroll
        for (int i = 0; i < 4; i++)
#pragma unroll
            for (int j = 0; j < 8; j++) acc[i][j] = fmaf(av[i], bv[j], acc[i][j]);
    }

#pragma unroll
    for (int i = 0; i < 4; i++) {
        int row = row0 + ty * 4 + i;
        if (row < n) {
            float4 o0 = make_float4(acc[i][0], acc[i][1], acc[i][2], acc[i][3]);
            float4 o1 = make_float4(acc[i][4], acc[i][5], acc[i][6], acc[i][7]);
            *(float4*)&g_h[row * OC + tx * 8]     = o0;
            *(float4*)&g_h[row * OC + tx * 8 + 4] = o1;
        }
    }
}

// ---------------- K2: per-(node,head) attention projections ----------------
__global__ void k_attproj(const float* __restrict__ att_src,
                          const float* __restrict__ att_dst, int n) {
    int idx = blockIdx.x * blockDim.x + threadIdx.x;
    if (idx >= n * HEADS) return;
    int hd = idx & (HEADS - 1);
    int node = idx >> 2;
    const float4* hrow = (const float4*)&g_h[node * OC + hd * OUT_DIM];
    float ssum = 0.f, dsum = 0.f;
#pragma unroll
    for (int i = 0; i < OUT_DIM / 4; i++) {
        float4 hv = hrow[i];
        float4 sv = *(const float4*)&att_src[hd * OUT_DIM + i * 4];
        float4 dv = *(const float4*)&att_dst[hd * OUT_DIM + i * 4];
        ssum += hv.x * sv.x + hv.y * sv.y + hv.z * sv.z + hv.w * sv.w;
        dsum += hv.x * dv.x + hv.y * dv.y + hv.z * dv.z + hv.w * dv.w;
    }
    g_asrc[idx] = ssum;
    g_adst[idx] = dsum;
}

// ---------------- K3: segment max over edges ----------------
__global__ void k_edge_max(const void* __restrict__ ei, int e) {
    int eidx = blockIdx.x * blockDim.x + threadIdx.x;
    if (eidx >= e) return;
    int2 sd = load_edge(ei, e, eidx);
    float4 as = *(const float4*)&g_asrc[sd.x * HEADS];
    float4 ad = *(const float4*)&g_adst[sd.y * HEADS];
    unsigned* mb = &g_mbits[sd.y * HEADS];
    atomicMax(&mb[0], enc_f(lrelu(as.x + ad.x)));
    atomicMax(&mb[1], enc_f(lrelu(as.y + ad.y)));
    atomicMax(&mb[2], enc_f(lrelu(as.z + ad.z)));
    atomicMax(&mb[3], enc_f(lrelu(as.w + ad.w)));
}

// ---------------- K4: segment sum of exp ----------------
__global__ void k_edge_sum(const void* __restrict__ ei, int e) {
    int eidx = blockIdx.x * blockDim.x + threadIdx.x;
    if (eidx >= e) return;
    int2 sd = load_edge(ei, e, eidx);
    float4 as = *(const float4*)&g_asrc[sd.x * HEADS];
    float4 ad = *(const float4*)&g_adst[sd.y * HEADS];
    uint4 mb = *(const uint4*)&g_mbits[sd.y * HEADS];
    float4 ex;
    ex.x = __expf(lrelu(as.x + ad.x) - dec_f(mb.x));
    ex.y = __expf(lrelu(as.y + ad.y) - dec_f(mb.y));
    ex.z = __expf(lrelu(as.z + ad.z) - dec_f(mb.z));
    ex.w = __expf(lrelu(as.w + ad.w) - dec_f(mb.w));
    red_add_v4(&g_s[sd.y * HEADS], ex);
}

// ---------------- K5: normalize + scatter messages (one warp per edge) ----------------
__global__ void k_scatter(const void* __restrict__ ei,
                          float* __restrict__ out, float* __restrict__ pooled, int e) {
    int gtid = blockIdx.x * blockDim.x + threadIdx.x;
    int eidx = gtid >> 5;
    if (eidx >= e) return;
    int lane = threadIdx.x & 31;
    int2 sd = load_edge(ei, e, eidx);
    int hd = lane >> 3;  // head for this lane's 4 output cols

    float a  = g_asrc[sd.x * HEADS + hd] + g_adst[sd.y * HEADS + hd];
    float m  = dec_f(g_mbits[sd.y * HEADS + hd]);
    float sv = g_s[sd.y * HEADS + hd];
    float alpha = __expf(lrelu(a) - m) / (sv + EPS_F);

    float4 v = *(const float4*)&g_h[sd.x * OC + lane * 4];
    v.x *= alpha; v.y *= alpha; v.z *= alpha; v.w *= alpha;
    red_add_v4(&out[sd.y * OC + lane * 4], v);

    // pooled = mean over heads: lanes 0,8,16,24 hold distinct heads
    float p = ((lane & 7) == 0) ? alpha : 0.f;
    p += __shfl_down_sync(0xffffffffu, p, 16);
    p += __shfl_down_sync(0xffffffffu, p, 8);
    if (lane == 0) pooled[eidx] = p * 0.25f;
}

// ---------------- launch ----------------
extern "C" void kernel_launch(void* const* d_in, const int* in_sizes, int n_in,
                              void* d_out, int out_size) {
    const float* x       = (const float*)d_in[0];
    const void*  ei      = d_in[1];
    const float* W       = (const float*)d_in[2];
    const float* att_src = (const float*)d_in[3];
    const float* att_dst = (const float*)d_in[4];
    const float* bias    = (const float*)d_in[5];

    int n = in_sizes[0] / IN_DIM;
    int e = in_sizes[1] / 2;

    float* out    = (float*)d_out;
    float* pooled = (float*)d_out + (size_t)n * OC;

    int smem = (IN_DIM * WS_S + IN_DIM * XS_S) * sizeof(float);  // ~100 KB
    cudaFuncSetAttribute(k_gemm, cudaFuncAttributeMaxDynamicSharedMemorySize, smem);

    k_detect<<<1, 32>>>((const unsigned*)ei);
    k_init<<<(n * OC + 255) / 256, 256>>>(bias, out, n);
    k_gemm<<<(n + TM - 1) / TM, 256, smem>>>(x, W, n);
    k_attproj<<<(n * HEADS + 255) / 256, 256>>>(att_src, att_dst, n);
    k_edge_max<<<(e + 255) / 256, 256>>>(ei, e);
    k_edge_sum<<<(e + 255) / 256, 256>>>(ei, e);
    k_scatter<<<((size_t)e * 32 + 255) / 256, 256>>>(ei, out, pooled, e);
}